// round 16
// baseline (speedup 1.0000x reference)
#include <cuda_runtime.h>
#include <cuda_fp16.h>
#include <cstdint>

// ---------------------------------------------------------------------------
// GIN layer:  out = BN( MLP( x + scatter_sum(x[src] -> dst) ) ) + x
// Round 16: R14 config (best known-good: 141.2us, rel_err 4.46e-4) +
//   graph-level parallelism: k_conv (W/x -> fp16) on a forked side stream
//   concurrent with hist -> scan -> fill; join before k_agg.
//   (R15's HADD2 + last-CTA-bnparam reverted: both neutral/negative.)
// ---------------------------------------------------------------------------

#define DIM 512
#define NMAX 10000
#define EMAX 160000
#define PARTS 160   // ceil(10000/64) = 157 used

typedef __half fp16;

// ---- scratch (device globals; no allocations allowed) ----
__device__ int g_deg[NMAX];          // zeroed by k_scan after use (replay-safe)
__device__ int g_off[NMAX + 1];
__device__ int g_cur[NMAX];
__device__ int g_csr[EMAX];

__device__ __align__(16) fp16 g_xh[NMAX * DIM];   // fp16 copy of x (L2-warm)
__device__ __align__(16) fp16 g_h0[NMAX * DIM];
__device__ __align__(16) fp16 g_h1[NMAX * DIM];
__device__ __align__(16) fp16 g_h2h[NMAX * DIM];  // fp16 h2 (pre-BN MLP out)
__device__ __align__(16) fp16 g_wt1[DIM * DIM];   // transposed: [n][k]
__device__ __align__(16) fp16 g_wt2[DIM * DIM];

__device__ __align__(16) float g_parts[PARTS][DIM];
__device__ __align__(16) float g_partq[PARTS][DIM];
__device__ __align__(16) float g_scale[DIM];
__device__ __align__(16) float g_shift[DIM];

// ---------------------------------------------------------------------------
// helpers
// ---------------------------------------------------------------------------
__device__ __forceinline__ void mma_f16(float* d, const unsigned* a, const unsigned* b) {
    asm volatile(
        "mma.sync.aligned.m16n8k16.row.col.f32.f16.f16.f32 "
        "{%0,%1,%2,%3}, {%4,%5,%6,%7}, {%8,%9}, {%0,%1,%2,%3};\n"
        : "+f"(d[0]), "+f"(d[1]), "+f"(d[2]), "+f"(d[3])
        : "r"(a[0]), "r"(a[1]), "r"(a[2]), "r"(a[3]), "r"(b[0]), "r"(b[1]));
}

__device__ __forceinline__ void ldsm4(unsigned* r, uint32_t saddr) {
    asm volatile(
        "ldmatrix.sync.aligned.m8n8.x4.shared.b16 {%0,%1,%2,%3}, [%4];\n"
        : "=r"(r[0]), "=r"(r[1]), "=r"(r[2]), "=r"(r[3])
        : "r"(saddr));
}

__device__ __forceinline__ void cp16(uint32_t saddr, const void* gaddr, int srcsize) {
    asm volatile("cp.async.cg.shared.global [%0], [%1], 16, %2;\n"
                 :: "r"(saddr), "l"(gaddr), "r"(srcsize));
}
__device__ __forceinline__ void cp_commit() {
    asm volatile("cp.async.commit_group;\n" ::: "memory");
}
__device__ __forceinline__ void cp_wait2() {
    asm volatile("cp.async.wait_group 2;\n" ::: "memory");
}

// add 8 halves (uint4) into two float4 accumulators
__device__ __forceinline__ void h8_add(float4& lo, float4& hi, uint4 v) {
    float2 f0 = __half22float2(*(__half2*)&v.x);
    float2 f1 = __half22float2(*(__half2*)&v.y);
    float2 f2 = __half22float2(*(__half2*)&v.z);
    float2 f3 = __half22float2(*(__half2*)&v.w);
    lo.x += f0.x; lo.y += f0.y; lo.z += f1.x; lo.w += f1.y;
    hi.x += f2.x; hi.y += f2.y; hi.z += f3.x; hi.w += f3.y;
}

__device__ __forceinline__ uint4 f8_pack(float4 lo, float4 hi) {
    __half2 h0 = __halves2half2(__float2half_rn(lo.x), __float2half_rn(lo.y));
    __half2 h1 = __halves2half2(__float2half_rn(lo.z), __float2half_rn(lo.w));
    __half2 h2 = __halves2half2(__float2half_rn(hi.x), __float2half_rn(hi.y));
    __half2 h3 = __halves2half2(__float2half_rn(hi.z), __float2half_rn(hi.w));
    uint4 r;
    r.x = *(uint32_t*)&h0; r.y = *(uint32_t*)&h1;
    r.z = *(uint32_t*)&h2; r.w = *(uint32_t*)&h3;
    return r;
}

// ---------------------------------------------------------------------------
// conversions (side stream): weights -> fp16 transposed, x -> fp16
// ---------------------------------------------------------------------------
__global__ void k_conv(const float* __restrict__ W1, const float* __restrict__ W2,
                       const float* __restrict__ x, int n) {
    int i = blockIdx.x * blockDim.x + threadIdx.x;
    if (i < DIM * DIM) {
        int k = i / DIM, nn = i % DIM;
        g_wt1[nn * DIM + k] = __float2half_rn(W1[i]);
        g_wt2[nn * DIM + k] = __float2half_rn(W2[i]);
    }
    if (i < n * 128) {
        float4 v = ((const float4*)x)[i];
        __half2 lo = __halves2half2(__float2half_rn(v.x), __float2half_rn(v.y));
        __half2 hi = __halves2half2(__float2half_rn(v.z), __float2half_rn(v.w));
        uint2 pk;
        pk.x = *(uint32_t*)&lo;
        pk.y = *(uint32_t*)&hi;
        ((uint2*)g_xh)[i] = pk;
    }
}

// degree histogram (main stream); g_deg pre-zeroed (module load / k_scan reset)
__global__ void k_hist(const int* __restrict__ dst, int e) {
    int i = blockIdx.x * blockDim.x + threadIdx.x;
    if (i < e) atomicAdd(&g_deg[dst[i]], 1);
}

// single-block one-shot scan; zeroes g_deg for next replay; g_off[n] = total.
#define STRIP 10
__global__ void __launch_bounds__(1024) k_scan(int n) {
    __shared__ int sdeg[NMAX + 240];
    __shared__ int wsum[32];
    int t = threadIdx.x, lane = t & 31, w = t >> 5;

    for (int idx = t; idx < n; idx += 1024) {
        sdeg[idx] = g_deg[idx];
        g_deg[idx] = 0;
    }
    __syncthreads();

    int base = t * STRIP;
    int loc[STRIP];
    int s = 0;
    #pragma unroll
    for (int j = 0; j < STRIP; j++) {
        int idx = base + j;
        int v = (idx < n) ? sdeg[idx] : 0;
        loc[j] = s;
        s += v;
    }
    int x = s;
    #pragma unroll
    for (int o = 1; o < 32; o <<= 1) {
        int y = __shfl_up_sync(0xffffffffu, x, o);
        if (lane >= o) x += y;
    }
    if (lane == 31) wsum[w] = x;
    __syncthreads();
    if (w == 0) {
        int sv = wsum[lane];
        #pragma unroll
        for (int o = 1; o < 32; o <<= 1) {
            int y = __shfl_up_sync(0xffffffffu, sv, o);
            if (lane >= o) sv += y;
        }
        wsum[lane] = sv;
    }
    __syncthreads();
    int excl = x - s + (w > 0 ? wsum[w - 1] : 0);
    #pragma unroll
    for (int j = 0; j < STRIP; j++) {
        int idx = base + j;
        if (idx < n) {
            int o = excl + loc[j];
            g_off[idx] = o;
            g_cur[idx] = o;
        }
    }
    if (t == 0) g_off[n] = wsum[31];
}

__global__ void k_fill(const int* __restrict__ src, const int* __restrict__ dst, int e) {
    int i = blockIdx.x * blockDim.x + threadIdx.x;
    if (i < e) {
        int p = atomicAdd(&g_cur[dst[i]], 1);
        g_csr[p] = src[i];
    }
}

// ---------------------------------------------------------------------------
// aggregation: TWO warps per node; each warp owns half the row (1 uint4/lane).
// h0[i] = fp16( xh[i] + sum_{j in sorted N(i)} xh[j] ), fp32 accumulate.
// ---------------------------------------------------------------------------
__global__ void __launch_bounds__(128) k_agg(int n) {
    __shared__ int nb[4][128];
    const int w = threadIdx.x >> 5, lane = threadIdx.x & 31;
    const int node = blockIdx.x * 2 + (w >> 1);
    const int half = w & 1;
    if (node >= n) return;
    const uint4* xh = (const uint4*)g_xh;           // 64 uint4 per row
    const int col = half * 32 + lane;
    const int s = g_off[node];
    const int d = g_off[node + 1] - s;
    int* mynb = nb[w];

    float4 alo = make_float4(0, 0, 0, 0), ahi = alo;
    h8_add(alo, ahi, xh[(size_t)node * 64 + col]);  // self

    const int dc = min(d, 128);
    for (int u = lane; u < dc; u += 32) mynb[u] = g_csr[s + u];
    __syncwarp();
    if (d <= 32) {
        int v = (lane < d) ? mynb[lane] : 0x7fffffff;
        #pragma unroll
        for (int k = 2; k <= 32; k <<= 1) {
            #pragma unroll
            for (int j = k >> 1; j > 0; j >>= 1) {
                int p = __shfl_xor_sync(0xffffffffu, v, j);
                bool up = ((lane & k) == 0);
                bool takemin = (((lane & j) == 0) == up);
                v = takemin ? min(v, p) : max(v, p);
            }
        }
        if (lane < d) mynb[lane] = v;
    } else if (lane == 0) {
        for (int a = 1; a < dc; a++) {
            int key = mynb[a];
            int b = a - 1;
            while (b >= 0 && mynb[b] > key) { mynb[b + 1] = mynb[b]; b--; }
            mynb[b + 1] = key;
        }
    }
    __syncwarp();

    int u = 0;
    for (; u + 8 <= dc; u += 8) {
        uint4 p0 = xh[(size_t)mynb[u + 0] * 64 + col];
        uint4 p1 = xh[(size_t)mynb[u + 1] * 64 + col];
        uint4 p2 = xh[(size_t)mynb[u + 2] * 64 + col];
        uint4 p3 = xh[(size_t)mynb[u + 3] * 64 + col];
        uint4 p4 = xh[(size_t)mynb[u + 4] * 64 + col];
        uint4 p5 = xh[(size_t)mynb[u + 5] * 64 + col];
        uint4 p6 = xh[(size_t)mynb[u + 6] * 64 + col];
        uint4 p7 = xh[(size_t)mynb[u + 7] * 64 + col];
        h8_add(alo, ahi, p0); h8_add(alo, ahi, p1);
        h8_add(alo, ahi, p2); h8_add(alo, ahi, p3);
        h8_add(alo, ahi, p4); h8_add(alo, ahi, p5);
        h8_add(alo, ahi, p6); h8_add(alo, ahi, p7);
    }
    if (u + 4 <= dc) {
        uint4 p0 = xh[(size_t)mynb[u + 0] * 64 + col];
        uint4 p1 = xh[(size_t)mynb[u + 1] * 64 + col];
        uint4 p2 = xh[(size_t)mynb[u + 2] * 64 + col];
        uint4 p3 = xh[(size_t)mynb[u + 3] * 64 + col];
        h8_add(alo, ahi, p0); h8_add(alo, ahi, p1);
        h8_add(alo, ahi, p2); h8_add(alo, ahi, p3);
        u += 4;
    }
    for (; u < dc; ++u)
        h8_add(alo, ahi, xh[(size_t)mynb[u] * 64 + col]);
    for (int uu = 128; uu < d; ++uu)
        h8_add(alo, ahi, xh[(size_t)g_csr[s + uu] * 64 + col]);

    ((uint4*)(g_h0 + (size_t)node * 512))[col] = f8_pack(alo, ahi);
}

// ---------------------------------------------------------------------------
// GEMM: C[M,512] = A[M,512] * W[512,512] (+bias), fp16 HMMA, fp32 accum.
//   BM=64, BN=128, BK=32; 8 warps (2x4), warp tile 32x32; 4-stage cp.async.
//   EPI==1: A=h0, B=wt1, epilogue bias+relu -> g_h1 (fp16)
//   EPI==0: A=h1, B=wt2, epilogue bias -> g_h2h (fp16) + fp32 BN partial stats
// ---------------------------------------------------------------------------
#define BM 64
#define NCHUNK 16              // 512 / BK(32)
#define ROWB 80                // bytes per smem row (64B data + 16B pad)
#define A_BYTES (BM * ROWB)    // 5120
#define B_BYTES (128 * ROWB)   // 10240
#define OFF_A 0
#define OFF_B A_BYTES
#define STAGE_BYTES (A_BYTES + B_BYTES)  // 15360
#define GEMM_SMEM (4 * STAGE_BYTES)      // 61440

template <int EPI>
__global__ void __launch_bounds__(256) k_gemm(const float* __restrict__ bias, int M) {
    extern __shared__ __align__(128) char sm[];

    const fp16* __restrict__ A = (EPI == 1) ? g_h0 : g_h1;
    const fp16* __restrict__ B = (EPI == 1) ? g_wt1 : g_wt2;

    const int t = threadIdx.x;
    const int m0 = blockIdx.y * BM;
    const int n0 = blockIdx.x * 128;
    const int lane = t & 31, wid = t >> 5;
    const int wm = (wid >> 2) * 32;     // 2 warp rows
    const int wn = (wid & 3) * 32;      // 4 warp cols
    const uint32_t smbase = (uint32_t)__cvta_generic_to_shared(sm);

    const int a_r = t >> 2, a_s = t & 3;
    const int arow = m0 + a_r;
    const int apred = (arow < M) ? 16 : 0;
    const uint32_t sA_off = (uint32_t)(a_r * ROWB + a_s * 16);
    const fp16* gA = A + (size_t)arow * 512 + a_s * 8;
    const int b_r = t >> 1, b_s = t & 1;
    const uint32_t sB_off = (uint32_t)(b_r * ROWB + b_s * 32);
    const fp16* gB = B + (size_t)(n0 + b_r) * 512 + b_s * 16;

    #define LOAD_CHUNK(c) do {                                                \
        uint32_t _sb = smbase + ((c) & 3) * STAGE_BYTES;                      \
        int _k0 = (c) * 32;                                                   \
        cp16(_sb + OFF_A + sA_off, gA + _k0,     apred);                      \
        cp16(_sb + OFF_B + sB_off,      gB + _k0,     16);                    \
        cp16(_sb + OFF_B + sB_off + 16, gB + _k0 + 8, 16);                    \
    } while (0)

    float acc[2][4][4];
    #pragma unroll
    for (int a = 0; a < 2; a++)
        #pragma unroll
        for (int b = 0; b < 4; b++)
            #pragma unroll
            for (int c = 0; c < 4; c++) acc[a][b][c] = 0.f;

    LOAD_CHUNK(0); cp_commit();
    LOAD_CHUNK(1); cp_commit();
    LOAD_CHUNK(2); cp_commit();

    for (int c = 0; c < NCHUNK; ++c) {
        cp_wait2();
        __syncthreads();
        if (c + 3 < NCHUNK) LOAD_CHUNK(c + 3);
        cp_commit();

        const uint32_t sb = smbase + (c & 3) * STAGE_BYTES;
        #pragma unroll
        for (int kk = 0; kk < 32; kk += 16) {
            unsigned bfr[4][2];
            #pragma unroll
            for (int g = 0; g < 2; g++) {
                int nr = wn + g * 16 + (lane & 7) + ((lane & 16) ? 8 : 0);
                int kc = kk + ((lane & 8) ? 8 : 0);
                unsigned r[4];
                ldsm4(r, sb + OFF_B + nr * ROWB + kc * 2);
                bfr[g*2][0] = r[0]; bfr[g*2][1] = r[1];
                bfr[g*2+1][0] = r[2]; bfr[g*2+1][1] = r[3];
            }
            #pragma unroll
            for (int mf = 0; mf < 2; mf++) {
                int ar = wm + mf * 16 + (lane & 15);
                int ac = kk + ((lane >> 4) << 3);
                unsigned ah[4];
                ldsm4(ah, sb + OFF_A + ar * ROWB + ac * 2);
                #pragma unroll
                for (int nf = 0; nf < 4; nf++) {
                    mma_f16(acc[mf][nf], ah, bfr[nf]);
                }
            }
        }
    }

    // ---- epilogue ----
    float csum[4][2], csq[4][2];
    if (EPI == 0) {
        #pragma unroll
        for (int nf = 0; nf < 4; nf++) { csum[nf][0] = csum[nf][1] = 0.f;
                                         csq[nf][0] = csq[nf][1] = 0.f; }
    }

    #pragma unroll
    for (int mf = 0; mf < 2; mf++) {
        #pragma unroll
        for (int nf = 0; nf < 4; nf++) {
            int col = n0 + wn + nf * 8 + (lane & 3) * 2;
            float b0 = bias[col], b1 = bias[col + 1];
            #pragma unroll
            for (int h = 0; h < 2; h++) {
                int row = m0 + wm + mf * 16 + (lane >> 2) + h * 8;
                if (row < M) {
                    float v0 = acc[mf][nf][h * 2 + 0] + b0;
                    float v1 = acc[mf][nf][h * 2 + 1] + b1;
                    if (EPI == 1) {
                        v0 = fmaxf(v0, 0.f);
                        v1 = fmaxf(v1, 0.f);
                        __half2 hv = __halves2half2(__float2half_rn(v0),
                                                    __float2half_rn(v1));
                        *(__half2*)(g_h1 + (size_t)row * 512 + col) = hv;
                    } else {
                        // stats from fp32 values BEFORE fp16 rounding
                        csum[nf][0] += v0; csum[nf][1] += v1;
                        csq[nf][0] += v0 * v0; csq[nf][1] += v1 * v1;
                        __half2 hv = __halves2half2(__float2half_rn(v0),
                                                    __float2half_rn(v1));
                        *(__half2*)(g_h2h + (size_t)row * 512 + col) = hv;
                    }
                }
            }
        }
    }

    if (EPI == 0) {
        #pragma unroll
        for (int nf = 0; nf < 4; nf++)
            #pragma unroll
            for (int j = 0; j < 2; j++) {
                #pragma unroll
                for (int off = 16; off >= 4; off >>= 1) {
                    csum[nf][j] += __shfl_down_sync(0xffffffffu, csum[nf][j], off);
                    csq[nf][j]  += __shfl_down_sync(0xffffffffu, csq[nf][j], off);
                }
            }
        float* s_red = (float*)sm;
        __syncthreads();
        if (wid < 4 && (lane >> 2) == 0) {
            #pragma unroll
            for (int nf = 0; nf < 4; nf++)
                #pragma unroll
                for (int j = 0; j < 2; j++) {
                    int cit = wn + nf * 8 + (lane & 3) * 2 + j;
                    s_red[cit] = csum[nf][j];
                    s_red[128 + cit] = csq[nf][j];
                }
        }
        __syncthreads();
        if (wid >= 4 && (lane >> 2) == 0) {
            #pragma unroll
            for (int nf = 0; nf < 4; nf++)
                #pragma unroll
                for (int j = 0; j < 2; j++) {
                    int cit = wn + nf * 8 + (lane & 3) * 2 + j;
                    g_parts[blockIdx.y][n0 + cit] = s_red[cit] + csum[nf][j];
                    g_partq[blockIdx.y][n0 + cit] = s_red[128 + cit] + csq[nf][j];
                }
        }
    }
    #undef LOAD_CHUNK
}

// ---------------------------------------------------------------------------
// BN params + output
// ---------------------------------------------------------------------------
__global__ void k_bnparam(const float* __restrict__ gamma, const float* __restrict__ beta,
                          float invn, int nparts) {
    int c = blockIdx.x * blockDim.x + threadIdx.x;
    if (c >= DIM) return;
    float s = 0, q = 0;
    for (int p = 0; p < nparts; p++) { s += g_parts[p][c]; q += g_partq[p][c]; }
    float mean = s * invn;
    float var = q * invn - mean * mean;
    float sc = gamma[c] * rsqrtf(var + 1e-5f);
    g_scale[c] = sc;
    g_shift[c] = beta[c] - mean * sc;
}

// out = h2*scale + shift + x ; h2,x read as L2-warm fp16, compute fp32.
__global__ void k_out(float* __restrict__ out, int n) {
    int i = blockIdx.x * blockDim.x + threadIdx.x;   // one float4 (4 cols)
    if (i >= n * 128) return;
    int c4 = i & 127;
    uint2 hp = ((const uint2*)g_h2h)[i];
    uint2 xp = ((const uint2*)g_xh)[i];
    float2 h01 = __half22float2(*(__half2*)&hp.x);
    float2 h23 = __half22float2(*(__half2*)&hp.y);
    float2 x01 = __half22float2(*(__half2*)&xp.x);
    float2 x23 = __half22float2(*(__half2*)&xp.y);
    float4 sc = ((const float4*)g_scale)[c4];
    float4 sh = ((const float4*)g_shift)[c4];
    float4 o;
    o.x = h01.x * sc.x + sh.x + x01.x;
    o.y = h01.y * sc.y + sh.y + x01.y;
    o.z = h23.x * sc.z + sh.z + x23.x;
    o.w = h23.y * sc.w + sh.w + x23.y;
    ((float4*)out)[i] = o;
}

// ---------------------------------------------------------------------------
extern "C" void kernel_launch(void* const* d_in, const int* in_sizes, int n_in,
                              void* d_out, int out_size) {
    const float* x     = (const float*)d_in[0];
    const int*   ei    = (const int*)d_in[1];
    const float* W1    = (const float*)d_in[2];
    const float* b1    = (const float*)d_in[3];
    const float* W2    = (const float*)d_in[4];
    const float* b2    = (const float*)d_in[5];
    const float* gamma = (const float*)d_in[6];
    const float* beta  = (const float*)d_in[7];
    float* out = (float*)d_out;

    int n = in_sizes[0] / DIM;
    int e = in_sizes[1] / 2;
    const int* src = ei;
    const int* dst = ei + e;

    static cudaStream_t s2 = nullptr;
    static cudaEvent_t evFork = nullptr, evJoin = nullptr;
    static bool init_done = false;
    if (!init_done) {
        cudaFuncSetAttribute(k_gemm<1>, cudaFuncAttributeMaxDynamicSharedMemorySize, GEMM_SMEM);
        cudaFuncSetAttribute(k_gemm<0>, cudaFuncAttributeMaxDynamicSharedMemorySize, GEMM_SMEM);
        cudaStreamCreateWithFlags(&s2, cudaStreamNonBlocking);
        cudaEventCreateWithFlags(&evFork, cudaEventDisableTiming);
        cudaEventCreateWithFlags(&evJoin, cudaEventDisableTiming);
        init_done = true;
    }

    // fork: conversions run on s2 concurrent with hist->scan->fill
    cudaEventRecord(evFork, 0);
    cudaStreamWaitEvent(s2, evFork, 0);
    int conv_threads = n * 128;             // covers x-convert and weights
    k_conv<<<(conv_threads + 255) / 256, 256, 0, s2>>>(W1, W2, x, n);

    k_hist<<<(e + 255) / 256, 256>>>(dst, e);
    k_scan<<<1, 1024>>>(n);
    k_fill<<<(e + 255) / 256, 256>>>(src, dst, e);

    // join: k_agg needs g_xh (s2) and g_csr (main)
    cudaEventRecord(evJoin, s2);
    cudaStreamWaitEvent(0, evJoin, 0);

    k_agg<<<(n + 1) / 2, 128>>>(n);

    int gy = (n + BM - 1) / BM;             // 157
    dim3 gg(4, gy);
    k_gemm<1><<<gg, 256, GEMM_SMEM>>>(b1, n);
    k_gemm<0><<<gg, 256, GEMM_SMEM>>>(b2, n);

    k_bnparam<<<2, 256>>>(gamma, beta, 1.0f / (float)n, gy);
    k_out<<<(n * 128 + 255) / 256, 256>>>(out, n);
}

// round 17
// speedup vs baseline: 1.0386x; 1.0386x over previous
#include <cuda_runtime.h>
#include <cuda_fp16.h>
#include <cstdint>

// ---------------------------------------------------------------------------
// GIN layer:  out = BN( MLP( x + scatter_sum(x[src] -> dst) ) ) + x
// Round 17: R14 config (141.2us, rel_err 4.46e-4) with higher-occupancy GEMM:
//   3-stage cp.async (validated distance-2 / wait_group 1 pipeline) +
//   __launch_bounds__(256,4) -> 4 CTAs/SM -> 1.06 waves (was 3 CTAs, 1.41).
//   (R16 stream fork reverted: contention regression.)
// ---------------------------------------------------------------------------

#define DIM 512
#define NMAX 10000
#define EMAX 160000
#define PARTS 160   // ceil(10000/64) = 157 used

typedef __half fp16;

// ---- scratch (device globals; no allocations allowed) ----
__device__ int g_deg[NMAX];          // zeroed by k_scan after use (replay-safe)
__device__ int g_off[NMAX + 1];
__device__ int g_cur[NMAX];
__device__ int g_csr[EMAX];

__device__ __align__(16) fp16 g_xh[NMAX * DIM];   // fp16 copy of x (L2-warm)
__device__ __align__(16) fp16 g_h0[NMAX * DIM];
__device__ __align__(16) fp16 g_h1[NMAX * DIM];
__device__ __align__(16) fp16 g_h2h[NMAX * DIM];  // fp16 h2 (pre-BN MLP out)
__device__ __align__(16) fp16 g_wt1[DIM * DIM];   // transposed: [n][k]
__device__ __align__(16) fp16 g_wt2[DIM * DIM];

__device__ __align__(16) float g_parts[PARTS][DIM];
__device__ __align__(16) float g_partq[PARTS][DIM];
__device__ __align__(16) float g_scale[DIM];
__device__ __align__(16) float g_shift[DIM];

// ---------------------------------------------------------------------------
// helpers
// ---------------------------------------------------------------------------
__device__ __forceinline__ void mma_f16(float* d, const unsigned* a, const unsigned* b) {
    asm volatile(
        "mma.sync.aligned.m16n8k16.row.col.f32.f16.f16.f32 "
        "{%0,%1,%2,%3}, {%4,%5,%6,%7}, {%8,%9}, {%0,%1,%2,%3};\n"
        : "+f"(d[0]), "+f"(d[1]), "+f"(d[2]), "+f"(d[3])
        : "r"(a[0]), "r"(a[1]), "r"(a[2]), "r"(a[3]), "r"(b[0]), "r"(b[1]));
}

__device__ __forceinline__ void ldsm4(unsigned* r, uint32_t saddr) {
    asm volatile(
        "ldmatrix.sync.aligned.m8n8.x4.shared.b16 {%0,%1,%2,%3}, [%4];\n"
        : "=r"(r[0]), "=r"(r[1]), "=r"(r[2]), "=r"(r[3])
        : "r"(saddr));
}

__device__ __forceinline__ void cp16(uint32_t saddr, const void* gaddr, int srcsize) {
    asm volatile("cp.async.cg.shared.global [%0], [%1], 16, %2;\n"
                 :: "r"(saddr), "l"(gaddr), "r"(srcsize));
}
__device__ __forceinline__ void cp_commit() {
    asm volatile("cp.async.commit_group;\n" ::: "memory");
}
__device__ __forceinline__ void cp_wait1() {
    asm volatile("cp.async.wait_group 1;\n" ::: "memory");
}

// add 8 halves (uint4) into two float4 accumulators
__device__ __forceinline__ void h8_add(float4& lo, float4& hi, uint4 v) {
    float2 f0 = __half22float2(*(__half2*)&v.x);
    float2 f1 = __half22float2(*(__half2*)&v.y);
    float2 f2 = __half22float2(*(__half2*)&v.z);
    float2 f3 = __half22float2(*(__half2*)&v.w);
    lo.x += f0.x; lo.y += f0.y; lo.z += f1.x; lo.w += f1.y;
    hi.x += f2.x; hi.y += f2.y; hi.z += f3.x; hi.w += f3.y;
}

__device__ __forceinline__ uint4 f8_pack(float4 lo, float4 hi) {
    __half2 h0 = __halves2half2(__float2half_rn(lo.x), __float2half_rn(lo.y));
    __half2 h1 = __halves2half2(__float2half_rn(lo.z), __float2half_rn(lo.w));
    __half2 h2 = __halves2half2(__float2half_rn(hi.x), __float2half_rn(hi.y));
    __half2 h3 = __halves2half2(__float2half_rn(hi.z), __float2half_rn(hi.w));
    uint4 r;
    r.x = *(uint32_t*)&h0; r.y = *(uint32_t*)&h1;
    r.z = *(uint32_t*)&h2; r.w = *(uint32_t*)&h3;
    return r;
}

// ---------------------------------------------------------------------------
// prep: weight convert + x->fp16 copy (warms L2 with g_xh) + degree histogram.
// ---------------------------------------------------------------------------
__global__ void k_prep(const float* __restrict__ W1, const float* __restrict__ W2,
                       const float* __restrict__ x, const int* __restrict__ dst,
                       int e, int n) {
    int i = blockIdx.x * blockDim.x + threadIdx.x;
    if (i < DIM * DIM) {
        int k = i / DIM, nn = i % DIM;
        g_wt1[nn * DIM + k] = __float2half_rn(W1[i]);
        g_wt2[nn * DIM + k] = __float2half_rn(W2[i]);
    }
    if (i < e) atomicAdd(&g_deg[dst[i]], 1);
    if (i < n * 128) {
        float4 v = ((const float4*)x)[i];
        __half2 lo = __halves2half2(__float2half_rn(v.x), __float2half_rn(v.y));
        __half2 hi = __halves2half2(__float2half_rn(v.z), __float2half_rn(v.w));
        uint2 pk;
        pk.x = *(uint32_t*)&lo;
        pk.y = *(uint32_t*)&hi;
        ((uint2*)g_xh)[i] = pk;
    }
}

// single-block one-shot scan; zeroes g_deg for next replay; g_off[n] = total.
#define STRIP 10
__global__ void __launch_bounds__(1024) k_scan(int n) {
    __shared__ int sdeg[NMAX + 240];
    __shared__ int wsum[32];
    int t = threadIdx.x, lane = t & 31, w = t >> 5;

    for (int idx = t; idx < n; idx += 1024) {
        sdeg[idx] = g_deg[idx];
        g_deg[idx] = 0;
    }
    __syncthreads();

    int base = t * STRIP;
    int loc[STRIP];
    int s = 0;
    #pragma unroll
    for (int j = 0; j < STRIP; j++) {
        int idx = base + j;
        int v = (idx < n) ? sdeg[idx] : 0;
        loc[j] = s;
        s += v;
    }
    int x = s;
    #pragma unroll
    for (int o = 1; o < 32; o <<= 1) {
        int y = __shfl_up_sync(0xffffffffu, x, o);
        if (lane >= o) x += y;
    }
    if (lane == 31) wsum[w] = x;
    __syncthreads();
    if (w == 0) {
        int sv = wsum[lane];
        #pragma unroll
        for (int o = 1; o < 32; o <<= 1) {
            int y = __shfl_up_sync(0xffffffffu, sv, o);
            if (lane >= o) sv += y;
        }
        wsum[lane] = sv;
    }
    __syncthreads();
    int excl = x - s + (w > 0 ? wsum[w - 1] : 0);
    #pragma unroll
    for (int j = 0; j < STRIP; j++) {
        int idx = base + j;
        if (idx < n) {
            int o = excl + loc[j];
            g_off[idx] = o;
            g_cur[idx] = o;
        }
    }
    if (t == 0) g_off[n] = wsum[31];
}

__global__ void k_fill(const int* __restrict__ src, const int* __restrict__ dst, int e) {
    int i = blockIdx.x * blockDim.x + threadIdx.x;
    if (i < e) {
        int p = atomicAdd(&g_cur[dst[i]], 1);
        g_csr[p] = src[i];
    }
}

// ---------------------------------------------------------------------------
// aggregation: TWO warps per node; each warp owns half the row (1 uint4/lane).
// h0[i] = fp16( xh[i] + sum_{j in sorted N(i)} xh[j] ), fp32 accumulate.
// ---------------------------------------------------------------------------
__global__ void __launch_bounds__(128) k_agg(int n) {
    __shared__ int nb[4][128];
    const int w = threadIdx.x >> 5, lane = threadIdx.x & 31;
    const int node = blockIdx.x * 2 + (w >> 1);
    const int half = w & 1;
    if (node >= n) return;
    const uint4* xh = (const uint4*)g_xh;           // 64 uint4 per row
    const int col = half * 32 + lane;
    const int s = g_off[node];
    const int d = g_off[node + 1] - s;
    int* mynb = nb[w];

    float4 alo = make_float4(0, 0, 0, 0), ahi = alo;
    h8_add(alo, ahi, xh[(size_t)node * 64 + col]);  // self

    const int dc = min(d, 128);
    for (int u = lane; u < dc; u += 32) mynb[u] = g_csr[s + u];
    __syncwarp();
    if (d <= 32) {
        int v = (lane < d) ? mynb[lane] : 0x7fffffff;
        #pragma unroll
        for (int k = 2; k <= 32; k <<= 1) {
            #pragma unroll
            for (int j = k >> 1; j > 0; j >>= 1) {
                int p = __shfl_xor_sync(0xffffffffu, v, j);
                bool up = ((lane & k) == 0);
                bool takemin = (((lane & j) == 0) == up);
                v = takemin ? min(v, p) : max(v, p);
            }
        }
        if (lane < d) mynb[lane] = v;
    } else if (lane == 0) {
        for (int a = 1; a < dc; a++) {
            int key = mynb[a];
            int b = a - 1;
            while (b >= 0 && mynb[b] > key) { mynb[b + 1] = mynb[b]; b--; }
            mynb[b + 1] = key;
        }
    }
    __syncwarp();

    int u = 0;
    for (; u + 8 <= dc; u += 8) {
        uint4 p0 = xh[(size_t)mynb[u + 0] * 64 + col];
        uint4 p1 = xh[(size_t)mynb[u + 1] * 64 + col];
        uint4 p2 = xh[(size_t)mynb[u + 2] * 64 + col];
        uint4 p3 = xh[(size_t)mynb[u + 3] * 64 + col];
        uint4 p4 = xh[(size_t)mynb[u + 4] * 64 + col];
        uint4 p5 = xh[(size_t)mynb[u + 5] * 64 + col];
        uint4 p6 = xh[(size_t)mynb[u + 6] * 64 + col];
        uint4 p7 = xh[(size_t)mynb[u + 7] * 64 + col];
        h8_add(alo, ahi, p0); h8_add(alo, ahi, p1);
        h8_add(alo, ahi, p2); h8_add(alo, ahi, p3);
        h8_add(alo, ahi, p4); h8_add(alo, ahi, p5);
        h8_add(alo, ahi, p6); h8_add(alo, ahi, p7);
    }
    if (u + 4 <= dc) {
        uint4 p0 = xh[(size_t)mynb[u + 0] * 64 + col];
        uint4 p1 = xh[(size_t)mynb[u + 1] * 64 + col];
        uint4 p2 = xh[(size_t)mynb[u + 2] * 64 + col];
        uint4 p3 = xh[(size_t)mynb[u + 3] * 64 + col];
        h8_add(alo, ahi, p0); h8_add(alo, ahi, p1);
        h8_add(alo, ahi, p2); h8_add(alo, ahi, p3);
        u += 4;
    }
    for (; u < dc; ++u)
        h8_add(alo, ahi, xh[(size_t)mynb[u] * 64 + col]);
    for (int uu = 128; uu < d; ++uu)
        h8_add(alo, ahi, xh[(size_t)g_csr[s + uu] * 64 + col]);

    ((uint4*)(g_h0 + (size_t)node * 512))[col] = f8_pack(alo, ahi);
}

// ---------------------------------------------------------------------------
// GEMM: C[M,512] = A[M,512] * W[512,512] (+bias), fp16 HMMA, fp32 accum.
//   BM=64, BN=128, BK=32; 8 warps (2x4), warp tile 32x32.
//   3-stage cp.async, prefetch distance 2, wait_group 1 (validated R13):
//     iter c: wait(chunk c) -> sync (stage (c+2)%3 free) -> load c+2 -> compute
//   __launch_bounds__(256,4): 4 CTAs/SM (regs<=64, smem 4x46KB=184KB) -> 1.06 waves.
//   EPI==1: A=h0, B=wt1, epilogue bias+relu -> g_h1 (fp16)
//   EPI==0: A=h1, B=wt2, epilogue bias -> g_h2h (fp16) + fp32 BN partial stats
// ---------------------------------------------------------------------------
#define BM 64
#define NCHUNK 16              // 512 / BK(32)
#define ROWB 80                // bytes per smem row (64B data + 16B pad)
#define A_BYTES (BM * ROWB)    // 5120
#define B_BYTES (128 * ROWB)   // 10240
#define OFF_A 0
#define OFF_B A_BYTES
#define STAGE_BYTES (A_BYTES + B_BYTES)  // 15360
#define GEMM_SMEM (3 * STAGE_BYTES)      // 46080

template <int EPI>
__global__ void __launch_bounds__(256, 4) k_gemm(const float* __restrict__ bias, int M) {
    extern __shared__ __align__(128) char sm[];

    const fp16* __restrict__ A = (EPI == 1) ? g_h0 : g_h1;
    const fp16* __restrict__ B = (EPI == 1) ? g_wt1 : g_wt2;

    const int t = threadIdx.x;
    const int m0 = blockIdx.y * BM;
    const int n0 = blockIdx.x * 128;
    const int lane = t & 31, wid = t >> 5;
    const int wm = (wid >> 2) * 32;     // 2 warp rows
    const int wn = (wid & 3) * 32;      // 4 warp cols
    const uint32_t smbase = (uint32_t)__cvta_generic_to_shared(sm);

    const int a_r = t >> 2, a_s = t & 3;
    const int arow = m0 + a_r;
    const int apred = (arow < M) ? 16 : 0;
    const uint32_t sA_off = (uint32_t)(a_r * ROWB + a_s * 16);
    const fp16* gA = A + (size_t)arow * 512 + a_s * 8;
    const int b_r = t >> 1, b_s = t & 1;
    const uint32_t sB_off = (uint32_t)(b_r * ROWB + b_s * 32);
    const fp16* gB = B + (size_t)(n0 + b_r) * 512 + b_s * 16;

    #define LOAD_CHUNK(c) do {                                                \
        uint32_t _sb = smbase + ((c) % 3) * STAGE_BYTES;                      \
        int _k0 = (c) * 32;                                                   \
        cp16(_sb + OFF_A + sA_off, gA + _k0,     apred);                      \
        cp16(_sb + OFF_B + sB_off,      gB + _k0,     16);                    \
        cp16(_sb + OFF_B + sB_off + 16, gB + _k0 + 8, 16);                    \
    } while (0)

    float acc[2][4][4];
    #pragma unroll
    for (int a = 0; a < 2; a++)
        #pragma unroll
        for (int b = 0; b < 4; b++)
            #pragma unroll
            for (int c = 0; c < 4; c++) acc[a][b][c] = 0.f;

    LOAD_CHUNK(0); cp_commit();
    LOAD_CHUNK(1); cp_commit();

    for (int c = 0; c < NCHUNK; ++c) {
        cp_wait1();          // chunk c resident (<=1 group outstanding)
        __syncthreads();     // all warps done with chunk c-1 -> stage (c+2)%3 free
        if (c + 2 < NCHUNK) LOAD_CHUNK(c + 2);
        cp_commit();

        const uint32_t sb = smbase + (c % 3) * STAGE_BYTES;
        #pragma unroll
        for (int kk = 0; kk < 32; kk += 16) {
            unsigned bfr[4][2];
            #pragma unroll
            for (int g = 0; g < 2; g++) {
                int nr = wn + g * 16 + (lane & 7) + ((lane & 16) ? 8 : 0);
                int kc = kk + ((lane & 8) ? 8 : 0);
                unsigned r[4];
                ldsm4(r, sb + OFF_B + nr * ROWB + kc * 2);
                bfr[g*2][0] = r[0]; bfr[g*2][1] = r[1];
                bfr[g*2+1][0] = r[2]; bfr[g*2+1][1] = r[3];
            }
            #pragma unroll
            for (int mf = 0; mf < 2; mf++) {
                int ar = wm + mf * 16 + (lane & 15);
                int ac = kk + ((lane >> 4) << 3);
                unsigned ah[4];
                ldsm4(ah, sb + OFF_A + ar * ROWB + ac * 2);
                #pragma unroll
                for (int nf = 0; nf < 4; nf++) {
                    mma_f16(acc[mf][nf], ah, bfr[nf]);
                }
            }
        }
    }

    // ---- epilogue ----
    float csum[4][2], csq[4][2];
    if (EPI == 0) {
        #pragma unroll
        for (int nf = 0; nf < 4; nf++) { csum[nf][0] = csum[nf][1] = 0.f;
                                         csq[nf][0] = csq[nf][1] = 0.f; }
    }

    #pragma unroll
    for (int mf = 0; mf < 2; mf++) {
        #pragma unroll
        for (int nf = 0; nf < 4; nf++) {
            int col = n0 + wn + nf * 8 + (lane & 3) * 2;
            float b0 = bias[col], b1 = bias[col + 1];
            #pragma unroll
            for (int h = 0; h < 2; h++) {
                int row = m0 + wm + mf * 16 + (lane >> 2) + h * 8;
                if (row < M) {
                    float v0 = acc[mf][nf][h * 2 + 0] + b0;
                    float v1 = acc[mf][nf][h * 2 + 1] + b1;
                    if (EPI == 1) {
                        v0 = fmaxf(v0, 0.f);
                        v1 = fmaxf(v1, 0.f);
                        __half2 hv = __halves2half2(__float2half_rn(v0),
                                                    __float2half_rn(v1));
                        *(__half2*)(g_h1 + (size_t)row * 512 + col) = hv;
                    } else {
                        // stats from fp32 values BEFORE fp16 rounding
                        csum[nf][0] += v0; csum[nf][1] += v1;
                        csq[nf][0] += v0 * v0; csq[nf][1] += v1 * v1;
                        __half2 hv = __halves2half2(__float2half_rn(v0),
                                                    __float2half_rn(v1));
                        *(__half2*)(g_h2h + (size_t)row * 512 + col) = hv;
                    }
                }
            }
        }
    }

    if (EPI == 0) {
        #pragma unroll
        for (int nf = 0; nf < 4; nf++)
            #pragma unroll
            for (int j = 0; j < 2; j++) {
                #pragma unroll
                for (int off = 16; off >= 4; off >>= 1) {
                    csum[nf][j] += __shfl_down_sync(0xffffffffu, csum[nf][j], off);
                    csq[nf][j]  += __shfl_down_sync(0xffffffffu, csq[nf][j], off);
                }
            }
        float* s_red = (float*)sm;
        __syncthreads();
        if (wid < 4 && (lane >> 2) == 0) {
            #pragma unroll
            for (int nf = 0; nf < 4; nf++)
                #pragma unroll
                for (int j = 0; j < 2; j++) {
                    int cit = wn + nf * 8 + (lane & 3) * 2 + j;
                    s_red[cit] = csum[nf][j];
                    s_red[128 + cit] = csq[nf][j];
                }
        }
        __syncthreads();
        if (wid >= 4 && (lane >> 2) == 0) {
            #pragma unroll
            for (int nf = 0; nf < 4; nf++)
                #pragma unroll
                for (int j = 0; j < 2; j++) {
                    int cit = wn + nf * 8 + (lane & 3) * 2 + j;
                    g_parts[blockIdx.y][n0 + cit] = s_red[cit] + csum[nf][j];
                    g_partq[blockIdx.y][n0 + cit] = s_red[128 + cit] + csq[nf][j];
                }
        }
    }
    #undef LOAD_CHUNK
}

// ---------------------------------------------------------------------------
// BN params + output
// ---------------------------------------------------------------------------
__global__ void k_bnparam(const float* __restrict__ gamma, const float* __restrict__ beta,
                          float invn, int nparts) {
    int c = blockIdx.x * blockDim.x + threadIdx.x;
    if (c >= DIM) return;
    float s = 0, q = 0;
    for (int p = 0; p < nparts; p++) { s += g_parts[p][c]; q += g_partq[p][c]; }
    float mean = s * invn;
    float var = q * invn - mean * mean;
    float sc = gamma[c] * rsqrtf(var + 1e-5f);
    g_scale[c] = sc;
    g_shift[c] = beta[c] - mean * sc;
}

// out = h2*scale + shift + x ; h2,x read as L2-warm fp16, compute fp32.
__global__ void k_out(float* __restrict__ out, int n) {
    int i = blockIdx.x * blockDim.x + threadIdx.x;   // one float4 (4 cols)
    if (i >= n * 128) return;
    int c4 = i & 127;
    uint2 hp = ((const uint2*)g_h2h)[i];
    uint2 xp = ((const uint2*)g_xh)[i];
    float2 h01 = __half22float2(*(__half2*)&hp.x);
    float2 h23 = __half22float2(*(__half2*)&hp.y);
    float2 x01 = __half22float2(*(__half2*)&xp.x);
    float2 x23 = __half22float2(*(__half2*)&xp.y);
    float4 sc = ((const float4*)g_scale)[c4];
    float4 sh = ((const float4*)g_shift)[c4];
    float4 o;
    o.x = h01.x * sc.x + sh.x + x01.x;
    o.y = h01.y * sc.y + sh.y + x01.y;
    o.z = h23.x * sc.z + sh.z + x23.x;
    o.w = h23.y * sc.w + sh.w + x23.y;
    ((float4*)out)[i] = o;
}

// ---------------------------------------------------------------------------
extern "C" void kernel_launch(void* const* d_in, const int* in_sizes, int n_in,
                              void* d_out, int out_size) {
    const float* x     = (const float*)d_in[0];
    const int*   ei    = (const int*)d_in[1];
    const float* W1    = (const float*)d_in[2];
    const float* b1    = (const float*)d_in[3];
    const float* W2    = (const float*)d_in[4];
    const float* b2    = (const float*)d_in[5];
    const float* gamma = (const float*)d_in[6];
    const float* beta  = (const float*)d_in[7];
    float* out = (float*)d_out;

    int n = in_sizes[0] / DIM;
    int e = in_sizes[1] / 2;
    const int* src = ei;
    const int* dst = ei + e;

    static bool attr_set = false;
    if (!attr_set) {
        cudaFuncSetAttribute(k_gemm<1>, cudaFuncAttributeMaxDynamicSharedMemorySize, GEMM_SMEM);
        cudaFuncSetAttribute(k_gemm<0>, cudaFuncAttributeMaxDynamicSharedMemorySize, GEMM_SMEM);
        attr_set = true;
    }

    int prep_threads = n * 128;             // covers x-convert, weights, hist
    k_prep<<<(prep_threads + 255) / 256, 256>>>(W1, W2, x, dst, e, n);
    k_scan<<<1, 1024>>>(n);
    k_fill<<<(e + 255) / 256, 256>>>(src, dst, e);
    k_agg<<<(n + 1) / 2, 128>>>(n);

    int gy = (n + BM - 1) / BM;             // 157
    dim3 gg(4, gy);
    k_gemm<1><<<gg, 256, GEMM_SMEM>>>(b1, n);
    k_gemm<0><<<gg, 256, GEMM_SMEM>>>(b2, n);

    k_bnparam<<<2, 256>>>(gamma, beta, 1.0f / (float)n, gy);
    k_out<<<(n * 128 + 255) / 256, 256>>>(out, n);
}